// round 9
// baseline (speedup 1.0000x reference)
#include <cuda_runtime.h>
#include <math_constants.h>

#define DIN 14
#define QN  256
#define SB  16
#define NC  7
#define DP  7      // dim-pairs = DIN/2

typedef unsigned long long u64;

// ---- device scratch (no allocations allowed) ----
// natural dim-pair k storage: g_kn[j*DP+i] = (k_j[2i], k_j[2i+1])
__device__ float2 g_kn[QN * DP];
__device__ float  g_c8[QN * 8];       // c[j][n] = Wm@(Wo@(Wv@LNpp(lookup_j))), padded to 8

// ---- packed f32x2 helpers (Blackwell dual-rate FP32, FFMA2) ----
__device__ __forceinline__ u64 fma2(u64 a, u64 b, u64 c) {
    u64 d;
    asm("fma.rn.f32x2 %0, %1, %2, %3;" : "=l"(d) : "l"(a), "l"(b), "l"(c));
    return d;
}
__device__ __forceinline__ u64 pack2(float lo, float hi) {
    u64 r; asm("mov.b64 %0, {%1, %2};" : "=l"(r) : "f"(lo), "f"(hi)); return r;
}
__device__ __forceinline__ void unpack2(u64 v, float& lo, float& hi) {
    asm("mov.b64 {%0, %1}, %2;" : "=f"(lo), "=f"(hi) : "l"(v));
}

// ============================================================
// Fused prep: block j LayerNorms pattern j (both LN variants),
// then computes c8[j] = Wm@(Wo@(Wv@vln_j)) and writes g_kn[j].
// ============================================================
__global__ __launch_bounds__(128) void prep_all(
    const float* __restrict__ lookup,
    const float* __restrict__ g_st, const float* __restrict__ b_st,
    const float* __restrict__ g_pp, const float* __restrict__ b_pp,
    const float* __restrict__ Wv,   const float* __restrict__ Wo,
    const float* __restrict__ Wm)
{
    int j = blockIdx.x;
    int t = threadIdx.x;
    __shared__ float sv[DIN];       // vln_j
    __shared__ float skk[DIN];      // LN_st'd pattern j
    __shared__ float sp[256];       // Wv @ vln
    __shared__ float shp[28][4];
    __shared__ float hh[28];

    // LN (every thread computes redundantly; thread<DIN writes)
    {
        float v[DIN];
        float mu = 0.f;
        #pragma unroll
        for (int d = 0; d < DIN; d++) { v[d] = lookup[j * DIN + d]; mu += v[d]; }
        mu *= (1.0f / DIN);
        float var = 0.f;
        #pragma unroll
        for (int d = 0; d < DIN; d++) { float dv = v[d] - mu; var += dv * dv; }
        float r = rsqrtf(var * (1.0f / DIN) + 1e-5f);
        if (t < DIN) {
            float c  = (v[t] - mu) * r;
            skk[t]   = c * g_st[t] + b_st[t];
            sv[t]    = c * g_pp[t] + b_pp[t];
        }
    }
    __syncthreads();

    // write k as dim-pairs
    if (t < DP) g_kn[j * DP + t] = make_float2(skk[2 * t], skk[2 * t + 1]);

    // p = Wv @ vln  (256 outputs, 2 per thread)
    #pragma unroll
    for (int rr = 0; rr < 2; rr++) {
        int row = t + rr * 128;
        float acc = 0.f;
        #pragma unroll
        for (int d = 0; d < DIN; d++) acc += Wv[row * DIN + d] * sv[d];
        sp[row] = acc;
    }
    __syncthreads();

    // h = Wo @ p  (28 outputs, 4-way split)
    if (t < 112) {
        int o = t >> 2, part = t & 3;
        float a = 0.f;
        int p0 = part * 64;
        #pragma unroll 8
        for (int p = p0; p < p0 + 64; p++) a += Wo[o * 256 + p] * sp[p];
        shp[o][part] = a;
    }
    __syncthreads();
    if (t < 28) hh[t] = shp[t][0] + shp[t][1] + shp[t][2] + shp[t][3];
    __syncthreads();

    // c = Wm @ h  (7 outputs, pad to 8)
    if (t < 8) {
        float a = 0.f;
        if (t < NC) {
            #pragma unroll
            for (int o = 0; o < 28; o++) a += Wm[t * 28 + o] * hh[o];
        }
        g_c8[j * 8 + t] = a;
    }
}

// ============================================================
// Main: 128 threads/block, 32 batch rows/block, 4 queries/thread.
// Dim-pair packing: fma2 accumulates (even-sum, odd-sum); one
// FADD per (query,pattern) folds to the dot. No q duplication
// -> 56 q-regs, no spills, 5 blocks/SM.
// ============================================================
__global__ __launch_bounds__(128, 5) void hopfield_main(
    const float* __restrict__ x,
    const float* __restrict__ g_sp, const float* __restrict__ b_sp,
    const float* __restrict__ bm,   const float* __restrict__ Wb,
    const float* __restrict__ bb,
    float* __restrict__ out, int B)
{
    __shared__ u64   sk[QN * DP];    // 14336 B, dim-pairs
    __shared__ float swb[SB];
    __shared__ float sg[DIN], sb[DIN];
    __shared__ float sbm[8];
    __shared__ float sbb;

    int t = threadIdx.x;
    {
        const u64* kg = (const u64*)g_kn;
        for (int i = t; i < QN * DP; i += 128) sk[i] = kg[i];
        if (t < SB)  swb[t] = Wb[t];
        if (t < DIN) { sg[t] = g_sp[t]; sb[t] = b_sp[t]; }
        if (t < NC)  sbm[t] = bm[t];
        if (t == 0)  { sbm[7] = 0.f; sbb = bb[0]; }
    }
    __syncthreads();

    int brow = blockIdx.x * 32 + (t >> 2);
    bool valid = (brow < B);
    int b = valid ? brow : (B - 1);
    int s0 = (t & 3) * 4;                 // 4 consecutive bands per thread

    const float* xp = x + ((size_t)b * SB + s0) * DIN;

    // ---- LayerNorm 4 queries; keep as dim-pair u64 (no duplication) ----
    u64 qp[4][DP];
    #pragma unroll
    for (int qq = 0; qq < 4; qq++) {
        const float2* p2 = (const float2*)(xp + qq * DIN);
        float v[DIN];
        #pragma unroll
        for (int i = 0; i < 7; i++) { float2 w = p2[i]; v[2*i] = w.x; v[2*i+1] = w.y; }
        float mu = 0.f;
        #pragma unroll
        for (int d = 0; d < DIN; d++) mu += v[d];
        mu *= (1.0f / DIN);
        float var = 0.f;
        #pragma unroll
        for (int d = 0; d < DIN; d++) { float dv = v[d] - mu; var += dv * dv; }
        float r = rsqrtf(var * (1.0f / DIN) + 1e-5f);
        #pragma unroll
        for (int i = 0; i < DP; i++) {
            float qlo = (v[2*i]   - mu) * r * sg[2*i]   + sb[2*i];
            float qhi = (v[2*i+1] - mu) * r * sg[2*i+1] + sb[2*i+1];
            qp[qq][i] = pack2(qlo, qhi);
        }
    }

    // ---- argmax over 256 patterns ----
    float maxv[4]; int idx[4];
    #pragma unroll
    for (int p = 0; p < 4; p++) { maxv[p] = -CUDART_INF_F; idx[p] = 0; }

    #pragma unroll 4
    for (int j = 0; j < QN; j++) {
        const u64* kj = sk + j * DP;
        u64 a0 = 0ull, a1 = 0ull, a2 = 0ull, a3 = 0ull;
        #pragma unroll
        for (int i = 0; i < DP; i++) {
            u64 kk = kj[i];              // LDS.64 broadcast: dims 2i,2i+1
            a0 = fma2(kk, qp[0][i], a0);
            a1 = fma2(kk, qp[1][i], a1);
            a2 = fma2(kk, qp[2][i], a2);
            a3 = fma2(kk, qp[3][i], a3);
        }
        // fold (even,odd) halves; carried dep = FMNMX only
        {
            float lo, hi; unpack2(a0, lo, hi);
            float pm = lo + hi;
            bool upd = pm > maxv[0];
            maxv[0] = fmaxf(maxv[0], pm);
            idx[0]  = upd ? j : idx[0];
        }
        {
            float lo, hi; unpack2(a1, lo, hi);
            float pm = lo + hi;
            bool upd = pm > maxv[1];
            maxv[1] = fmaxf(maxv[1], pm);
            idx[1]  = upd ? j : idx[1];
        }
        {
            float lo, hi; unpack2(a2, lo, hi);
            float pm = lo + hi;
            bool upd = pm > maxv[2];
            maxv[2] = fmaxf(maxv[2], pm);
            idx[2]  = upd ? j : idx[2];
        }
        {
            float lo, hi; unpack2(a3, lo, hi);
            float pm = lo + hi;
            bool upd = pm > maxv[3];
            maxv[3] = fmaxf(maxv[3], pm);
            idx[3]  = upd ? j : idx[3];
        }
    }

    // ---- head: z[n] = sum_s Wb[s]*c[idx(s)][n] (+bias), softmax over 7 ----
    float zp[NC];
    #pragma unroll
    for (int n = 0; n < NC; n++) zp[n] = 0.f;
    #pragma unroll
    for (int p = 0; p < 4; p++) {
        int id = idx[p];
        float w = swb[s0 + p];
        const float4* cr = (const float4*)(g_c8 + id * 8);
        float4 c0 = __ldg(cr);
        float4 c1 = __ldg(cr + 1);
        zp[0] += w * c0.x; zp[1] += w * c0.y; zp[2] += w * c0.z; zp[3] += w * c0.w;
        zp[4] += w * c1.x; zp[5] += w * c1.y; zp[6] += w * c1.z;
    }
    // combine the 4 quarter-row threads (t..t^3, same b, same warp)
    #pragma unroll
    for (int n = 0; n < NC; n++) {
        zp[n] += __shfl_xor_sync(0xffffffffu, zp[n], 1);
        zp[n] += __shfl_xor_sync(0xffffffffu, zp[n], 2);
    }

    if (valid && ((t & 3) == 0)) {
        float sumWb = 0.f;
        #pragma unroll
        for (int s = 0; s < SB; s++) sumWb += swb[s];
        float z[NC], zmax = -CUDART_INF_F;
        #pragma unroll
        for (int n = 0; n < NC; n++) {
            z[n] = zp[n] + sbm[n] * sumWb + sbb;
            zmax = fmaxf(zmax, z[n]);
        }
        float es = 0.f;
        #pragma unroll
        for (int n = 0; n < NC; n++) { z[n] = expf(z[n] - zmax); es += z[n]; }
        float inv = 1.0f / es;
        float* op = out + (size_t)b * NC;
        #pragma unroll
        for (int n = 0; n < NC; n++) op[n] = z[n] * inv;
    }
}

// ============================================================
extern "C" void kernel_launch(void* const* d_in, const int* in_sizes, int n_in,
                              void* d_out, int out_size) {
    const float* x      = (const float*)d_in[0];
    const float* lookup = (const float*)d_in[1];
    const float* g_st   = (const float*)d_in[2];
    const float* b_st   = (const float*)d_in[3];
    const float* g_sp   = (const float*)d_in[4];
    const float* b_sp   = (const float*)d_in[5];
    const float* g_pp   = (const float*)d_in[6];
    const float* b_pp   = (const float*)d_in[7];
    const float* Wv     = (const float*)d_in[8];
    const float* Wo     = (const float*)d_in[9];
    const float* Wm     = (const float*)d_in[10];
    const float* bm     = (const float*)d_in[11];
    const float* Wb     = (const float*)d_in[12];
    const float* bb     = (const float*)d_in[13];
    float* out = (float*)d_out;

    int B = in_sizes[0] / (SB * DIN);

    prep_all<<<QN, 128>>>(lookup, g_st, b_st, g_pp, b_pp, Wv, Wo, Wm);
    hopfield_main<<<(B + 31) / 32, 128>>>(x, g_sp, b_sp, bm, Wb, bb, out, B);
}

// round 11
// speedup vs baseline: 1.0156x; 1.0156x over previous
#include <cuda_runtime.h>
#include <math_constants.h>

#define DIN 14
#define QN  256
#define SB  16
#define NC  7

typedef unsigned long long u64;

// ---- device scratch (no allocations allowed) ----
// pattern-PAIRED k storage: g_kp[jp*DIN+d] = (k[2jp][d], k[2jp+1][d])
__device__ float2 g_kp[(QN / 2) * DIN];
__device__ float  g_c8[QN * 8];       // c[j][n] = Wm@(Wo@(Wv@LNpp(lookup_j))), padded to 8

// ---- packed f32x2 helpers (Blackwell dual-rate FP32, FFMA2) ----
__device__ __forceinline__ u64 fma2(u64 a, u64 b, u64 c) {
    u64 d;
    asm("fma.rn.f32x2 %0, %1, %2, %3;" : "=l"(d) : "l"(a), "l"(b), "l"(c));
    return d;
}
__device__ __forceinline__ u64 pack2(float lo, float hi) {
    u64 r; asm("mov.b64 %0, {%1, %2};" : "=l"(r) : "f"(lo), "f"(hi)); return r;
}
__device__ __forceinline__ void unpack2(u64 v, float& lo, float& hi) {
    asm("mov.b64 {%0, %1}, %2;" : "=f"(lo), "=f"(hi) : "l"(v));
}

// ============================================================
// Fused prep: block j LayerNorms pattern j (both LN variants),
// then computes c8[j] = Wm@(Wo@(Wv@vln_j)) and writes g_kp[j/2].
// ============================================================
__global__ __launch_bounds__(128) void prep_all(
    const float* __restrict__ lookup,
    const float* __restrict__ g_st, const float* __restrict__ b_st,
    const float* __restrict__ g_pp, const float* __restrict__ b_pp,
    const float* __restrict__ Wv,   const float* __restrict__ Wo,
    const float* __restrict__ Wm)
{
    int j = blockIdx.x;
    int t = threadIdx.x;
    __shared__ float sv[DIN];       // vln_j
    __shared__ float sp[256];       // Wv @ vln
    __shared__ float shp[28][4];
    __shared__ float hh[28];

    // LN (every thread computes redundantly; thread<DIN writes)
    {
        float v[DIN];
        float mu = 0.f;
        #pragma unroll
        for (int d = 0; d < DIN; d++) { v[d] = lookup[j * DIN + d]; mu += v[d]; }
        mu *= (1.0f / DIN);
        float var = 0.f;
        #pragma unroll
        for (int d = 0; d < DIN; d++) { float dv = v[d] - mu; var += dv * dv; }
        float r = rsqrtf(var * (1.0f / DIN) + 1e-5f);
        if (t < DIN) {
            float c  = (v[t] - mu) * r;
            float kn = c * g_st[t] + b_st[t];
            // interleaved write into the pattern-pair slot
            ((float*)g_kp)[(((j >> 1) * DIN) + t) * 2 + (j & 1)] = kn;
            sv[t] = c * g_pp[t] + b_pp[t];
        }
    }
    __syncthreads();

    // p = Wv @ vln  (256 outputs, 2 per thread)
    #pragma unroll
    for (int rr = 0; rr < 2; rr++) {
        int row = t + rr * 128;
        float acc = 0.f;
        #pragma unroll
        for (int d = 0; d < DIN; d++) acc += Wv[row * DIN + d] * sv[d];
        sp[row] = acc;
    }
    __syncthreads();

    // h = Wo @ p  (28 outputs, 4-way split)
    if (t < 112) {
        int o = t >> 2, part = t & 3;
        float a = 0.f;
        int p0 = part * 64;
        #pragma unroll 8
        for (int p = p0; p < p0 + 64; p++) a += Wo[o * 256 + p] * sp[p];
        shp[o][part] = a;
    }
    __syncthreads();
    if (t < 28) hh[t] = shp[t][0] + shp[t][1] + shp[t][2] + shp[t][3];
    __syncthreads();

    // c = Wm @ h  (7 outputs, pad to 8)
    if (t < 8) {
        float a = 0.f;
        if (t < NC) {
            #pragma unroll
            for (int o = 0; o < 28; o++) a += Wm[t * 28 + o] * hh[o];
        }
        g_c8[j * 8 + t] = a;
    }
}

// ============================================================
// Main: 128 threads/block, 16 batch rows/block, 2 queries/thread.
// k pattern-paired in smem (LDS.128 amortized); queries duplicated
// (q,q) in registers (56 regs). In-loop argmax tracks only
// (maxv, jp_best); the lo/hi pattern of the winning pair is
// disambiguated once after the loop. 5 blocks/SM target.
// ============================================================
__global__ __launch_bounds__(128, 5) void hopfield_main(
    const float* __restrict__ x,
    const float* __restrict__ g_sp, const float* __restrict__ b_sp,
    const float* __restrict__ bm,   const float* __restrict__ Wb,
    const float* __restrict__ bb,
    float* __restrict__ out, int B)
{
    __shared__ u64   sk[(QN / 2) * DIN];   // 14336 B, pattern pairs
    __shared__ float swb[SB];
    __shared__ float sg[DIN], sb[DIN];
    __shared__ float sbm[8];
    __shared__ float sbb;

    int t = threadIdx.x;
    {
        const u64* kg = (const u64*)g_kp;
        for (int i = t; i < (QN / 2) * DIN; i += 128) sk[i] = kg[i];
        if (t < SB)  swb[t] = Wb[t];
        if (t < DIN) { sg[t] = g_sp[t]; sb[t] = b_sp[t]; }
        if (t < NC)  sbm[t] = bm[t];
        if (t == 0)  { sbm[7] = 0.f; sbb = bb[0]; }
    }
    __syncthreads();

    int brow = blockIdx.x * 16 + (t >> 3);
    bool valid = (brow < B);
    int b = valid ? brow : (B - 1);
    int s0 = (t & 7) * 2;                 // 2 consecutive bands per thread

    const float* xp = x + ((size_t)b * SB + s0) * DIN;

    // ---- LayerNorm 2 queries; duplicate each into (q,q) u64 pairs ----
    u64 qd[2][DIN];
    #pragma unroll
    for (int qq = 0; qq < 2; qq++) {
        const float2* p2 = (const float2*)(xp + qq * DIN);
        float v[DIN];
        #pragma unroll
        for (int i = 0; i < 7; i++) { float2 w = p2[i]; v[2*i] = w.x; v[2*i+1] = w.y; }
        float mu = 0.f;
        #pragma unroll
        for (int d = 0; d < DIN; d++) mu += v[d];
        mu *= (1.0f / DIN);
        float var = 0.f;
        #pragma unroll
        for (int d = 0; d < DIN; d++) { float dv = v[d] - mu; var += dv * dv; }
        float r = rsqrtf(var * (1.0f / DIN) + 1e-5f);
        #pragma unroll
        for (int d = 0; d < DIN; d++) {
            float q = (v[d] - mu) * r * sg[d] + sb[d];
            qd[qq][d] = pack2(q, q);
        }
    }

    // ---- argmax over 128 pattern-pairs ----
    float maxv[2]; int jpb[2];
    maxv[0] = -CUDART_INF_F; maxv[1] = -CUDART_INF_F;
    jpb[0] = 0; jpb[1] = 0;

    const u64 z2 = pack2(0.f, 0.f);

    #pragma unroll 2
    for (int jp = 0; jp < QN / 2; jp++) {
        const ulonglong2* kp = (const ulonglong2*)(sk + jp * DIN);
        u64 a0 = z2, a1 = z2;
        #pragma unroll
        for (int i = 0; i < 7; i++) {
            ulonglong2 kk = kp[i];   // LDS.128: pattern-pair for dims 2i, 2i+1
            a0 = fma2(kk.x, qd[0][2*i],   a0);
            a1 = fma2(kk.x, qd[1][2*i],   a1);
            a0 = fma2(kk.y, qd[0][2*i+1], a0);
            a1 = fma2(kk.y, qd[1][2*i+1], a1);
        }
        // slim epilogue: carried dep = FMNMX; pair-id only
        {
            float lo, hi; unpack2(a0, lo, hi);
            float pm  = fmaxf(lo, hi);
            bool  upd = pm > maxv[0];
            maxv[0] = fmaxf(maxv[0], pm);
            jpb[0]  = upd ? jp : jpb[0];
        }
        {
            float lo, hi; unpack2(a1, lo, hi);
            float pm  = fmaxf(lo, hi);
            bool  upd = pm > maxv[1];
            maxv[1] = fmaxf(maxv[1], pm);
            jpb[1]  = upd ? jp : jpb[1];
        }
    }

    // ---- disambiguate lo/hi within winning pair (re-dot, deterministic) ----
    int idx[2];
    #pragma unroll
    for (int qq = 0; qq < 2; qq++) {
        const ulonglong2* kp = (const ulonglong2*)(sk + jpb[qq] * DIN);
        u64 a = z2;
        #pragma unroll
        for (int i = 0; i < 7; i++) {
            ulonglong2 kk = kp[i];
            a = fma2(kk.x, qd[qq][2*i],   a);
            a = fma2(kk.y, qd[qq][2*i+1], a);
        }
        float lo, hi; unpack2(a, lo, hi);
        idx[qq] = 2 * jpb[qq] + ((hi > lo) ? 1 : 0);
    }

    // ---- head: z[n] = sum_s Wb[s]*c[idx(s)][n] (+bias), softmax over 7 ----
    float zp[NC];
    #pragma unroll
    for (int n = 0; n < NC; n++) zp[n] = 0.f;
    #pragma unroll
    for (int p = 0; p < 2; p++) {
        int id = idx[p];
        float w = swb[s0 + p];
        const float4* cr = (const float4*)(g_c8 + id * 8);
        float4 c0 = __ldg(cr);
        float4 c1 = __ldg(cr + 1);
        zp[0] += w * c0.x; zp[1] += w * c0.y; zp[2] += w * c0.z; zp[3] += w * c0.w;
        zp[4] += w * c1.x; zp[5] += w * c1.y; zp[6] += w * c1.z;
    }
    // combine the 8 threads of this batch row (t..t^7, same warp)
    #pragma unroll
    for (int n = 0; n < NC; n++) {
        zp[n] += __shfl_xor_sync(0xffffffffu, zp[n], 1);
        zp[n] += __shfl_xor_sync(0xffffffffu, zp[n], 2);
        zp[n] += __shfl_xor_sync(0xffffffffu, zp[n], 4);
    }

    if (valid && ((t & 7) == 0)) {
        float sumWb = 0.f;
        #pragma unroll
        for (int s = 0; s < SB; s++) sumWb += swb[s];
        float z[NC], zmax = -CUDART_INF_F;
        #pragma unroll
        for (int n = 0; n < NC; n++) {
            z[n] = zp[n] + sbm[n] * sumWb + sbb;
            zmax = fmaxf(zmax, z[n]);
        }
        float es = 0.f;
        #pragma unroll
        for (int n = 0; n < NC; n++) { z[n] = expf(z[n] - zmax); es += z[n]; }
        float inv = 1.0f / es;
        float* op = out + (size_t)b * NC;
        #pragma unroll
        for (int n = 0; n < NC; n++) op[n] = z[n] * inv;
    }
}

// ============================================================
extern "C" void kernel_launch(void* const* d_in, const int* in_sizes, int n_in,
                              void* d_out, int out_size) {
    const float* x      = (const float*)d_in[0];
    const float* lookup = (const float*)d_in[1];
    const float* g_st   = (const float*)d_in[2];
    const float* b_st   = (const float*)d_in[3];
    const float* g_sp   = (const float*)d_in[4];
    const float* b_sp   = (const float*)d_in[5];
    const float* g_pp   = (const float*)d_in[6];
    const float* b_pp   = (const float*)d_in[7];
    const float* Wv     = (const float*)d_in[8];
    const float* Wo     = (const float*)d_in[9];
    const float* Wm     = (const float*)d_in[10];
    const float* bm     = (const float*)d_in[11];
    const float* Wb     = (const float*)d_in[12];
    const float* bb     = (const float*)d_in[13];
    float* out = (float*)d_out;

    int B = in_sizes[0] / (SB * DIN);

    prep_all<<<QN, 128>>>(lookup, g_st, b_st, g_pp, b_pp, Wv, Wo, Wm);
    hopfield_main<<<(B + 15) / 16, 128>>>(x, g_sp, b_sp, bm, Wb, bb, out, B);
}

// round 13
// speedup vs baseline: 1.1198x; 1.1026x over previous
#include <cuda_runtime.h>
#include <math_constants.h>

#define DIN 14
#define QN  256
#define SB  16
#define NC  7

typedef unsigned long long u64;

// ---- device scratch (no allocations allowed) ----
// pattern-PAIRED k storage: g_kp[jp*DIN+d] = (k[2jp][d], k[2jp+1][d])
__device__ float2 g_kp[(QN / 2) * DIN];
__device__ float  g_c8[QN * 8];       // c[j][n] = Wm@(Wo@(Wv@LNpp(lookup_j))), padded to 8

// ---- packed f32x2 helpers (Blackwell dual-rate FP32, FFMA2) ----
__device__ __forceinline__ u64 fma2(u64 a, u64 b, u64 c) {
    u64 d;
    asm("fma.rn.f32x2 %0, %1, %2, %3;" : "=l"(d) : "l"(a), "l"(b), "l"(c));
    return d;
}
__device__ __forceinline__ u64 pack2(float lo, float hi) {
    u64 r; asm("mov.b64 %0, {%1, %2};" : "=l"(r) : "f"(lo), "f"(hi)); return r;
}
__device__ __forceinline__ void unpack2(u64 v, float& lo, float& hi) {
    asm("mov.b64 {%0, %1}, %2;" : "=f"(lo), "=f"(hi) : "l"(v));
}

// ============================================================
// Fused prep: block j LayerNorms pattern j (both LN variants),
// then computes c8[j] = Wm@(Wo@(Wv@vln_j)) and writes g_kp[j/2].
// ============================================================
__global__ __launch_bounds__(128) void prep_all(
    const float* __restrict__ lookup,
    const float* __restrict__ g_st, const float* __restrict__ b_st,
    const float* __restrict__ g_pp, const float* __restrict__ b_pp,
    const float* __restrict__ Wv,   const float* __restrict__ Wo,
    const float* __restrict__ Wm)
{
    int j = blockIdx.x;
    int t = threadIdx.x;
    __shared__ float sv[DIN];       // vln_j
    __shared__ float sp[256];       // Wv @ vln
    __shared__ float shp[28][4];
    __shared__ float hh[28];

    // LN (every thread computes redundantly; thread<DIN writes)
    {
        float v[DIN];
        float mu = 0.f;
        #pragma unroll
        for (int d = 0; d < DIN; d++) { v[d] = lookup[j * DIN + d]; mu += v[d]; }
        mu *= (1.0f / DIN);
        float var = 0.f;
        #pragma unroll
        for (int d = 0; d < DIN; d++) { float dv = v[d] - mu; var += dv * dv; }
        float r = rsqrtf(var * (1.0f / DIN) + 1e-5f);
        if (t < DIN) {
            float c  = (v[t] - mu) * r;
            float kn = c * g_st[t] + b_st[t];
            // interleaved write into the pattern-pair slot
            ((float*)g_kp)[(((j >> 1) * DIN) + t) * 2 + (j & 1)] = kn;
            sv[t] = c * g_pp[t] + b_pp[t];
        }
    }
    __syncthreads();

    // p = Wv @ vln  (256 outputs, 2 per thread)
    #pragma unroll
    for (int rr = 0; rr < 2; rr++) {
        int row = t + rr * 128;
        float acc = 0.f;
        #pragma unroll
        for (int d = 0; d < DIN; d++) acc += Wv[row * DIN + d] * sv[d];
        sp[row] = acc;
    }
    __syncthreads();

    // h = Wo @ p  (28 outputs, 4-way split)
    if (t < 112) {
        int o = t >> 2, part = t & 3;
        float a = 0.f;
        int p0 = part * 64;
        #pragma unroll 8
        for (int p = p0; p < p0 + 64; p++) a += Wo[o * 256 + p] * sp[p];
        shp[o][part] = a;
    }
    __syncthreads();
    if (t < 28) hh[t] = shp[t][0] + shp[t][1] + shp[t][2] + shp[t][3];
    __syncthreads();

    // c = Wm @ h  (7 outputs, pad to 8)
    if (t < 8) {
        float a = 0.f;
        if (t < NC) {
            #pragma unroll
            for (int o = 0; o < 28; o++) a += Wm[t * 28 + o] * hh[o];
        }
        g_c8[j * 8 + t] = a;
    }
}

// ============================================================
// Main: 128 threads/block, 32 batch rows/block, 4 queries/thread.
// R8 structure (pattern-paired k, (q,q)-dup queries, 4 chains)
// with SLIM in-loop argmax: track (max, pair-id) only; the lo/hi
// pattern within the winning pair is disambiguated post-loop by
// one deterministic re-dot per query.
// ============================================================
__global__ __launch_bounds__(128, 4) void hopfield_main(
    const float* __restrict__ x,
    const float* __restrict__ g_sp, const float* __restrict__ b_sp,
    const float* __restrict__ bm,   const float* __restrict__ Wb,
    const float* __restrict__ bb,
    float* __restrict__ out, int B)
{
    __shared__ u64   sk[(QN / 2) * DIN];   // 14336 B, pattern pairs
    __shared__ float swb[SB];
    __shared__ float sg[DIN], sb[DIN];
    __shared__ float sbm[8];
    __shared__ float sbb;

    int t = threadIdx.x;
    {
        const u64* kg = (const u64*)g_kp;
        for (int i = t; i < (QN / 2) * DIN; i += 128) sk[i] = kg[i];
        if (t < SB)  swb[t] = Wb[t];
        if (t < DIN) { sg[t] = g_sp[t]; sb[t] = b_sp[t]; }
        if (t < NC)  sbm[t] = bm[t];
        if (t == 0)  { sbm[7] = 0.f; sbb = bb[0]; }
    }
    __syncthreads();

    int brow = blockIdx.x * 32 + (t >> 2);
    bool valid = (brow < B);
    int b = valid ? brow : (B - 1);
    int s0 = (t & 3) * 4;                 // 4 consecutive bands per thread

    const float* xp = x + ((size_t)b * SB + s0) * DIN;

    // ---- LayerNorm 4 queries; duplicate each into (q,q) u64 pairs ----
    u64 qd[4][DIN];
    #pragma unroll
    for (int qq = 0; qq < 4; qq++) {
        const float2* p2 = (const float2*)(xp + qq * DIN);
        float v[DIN];
        #pragma unroll
        for (int i = 0; i < 7; i++) { float2 w = p2[i]; v[2*i] = w.x; v[2*i+1] = w.y; }
        float mu = 0.f;
        #pragma unroll
        for (int d = 0; d < DIN; d++) mu += v[d];
        mu *= (1.0f / DIN);
        float var = 0.f;
        #pragma unroll
        for (int d = 0; d < DIN; d++) { float dv = v[d] - mu; var += dv * dv; }
        float r = rsqrtf(var * (1.0f / DIN) + 1e-5f);
        #pragma unroll
        for (int d = 0; d < DIN; d++) {
            float q = (v[d] - mu) * r * sg[d] + sb[d];
            qd[qq][d] = pack2(q, q);
        }
    }

    // ---- argmax over 128 pattern-pairs (slim: pair-id only) ----
    float maxv[4]; int jpb[4];
    #pragma unroll
    for (int p = 0; p < 4; p++) { maxv[p] = -CUDART_INF_F; jpb[p] = 0; }

    const u64 z2 = pack2(0.f, 0.f);

    #pragma unroll 2
    for (int jp = 0; jp < QN / 2; jp++) {
        const ulonglong2* kp = (const ulonglong2*)(sk + jp * DIN);
        u64 a0 = z2, a1 = z2, a2 = z2, a3 = z2;
        #pragma unroll
        for (int i = 0; i < 7; i++) {
            ulonglong2 kk = kp[i];   // LDS.128: pattern-pair for dims 2i, 2i+1
            a0 = fma2(kk.x, qd[0][2*i],   a0);
            a1 = fma2(kk.x, qd[1][2*i],   a1);
            a2 = fma2(kk.x, qd[2][2*i],   a2);
            a3 = fma2(kk.x, qd[3][2*i],   a3);
            a0 = fma2(kk.y, qd[0][2*i+1], a0);
            a1 = fma2(kk.y, qd[1][2*i+1], a1);
            a2 = fma2(kk.y, qd[2][2*i+1], a2);
            a3 = fma2(kk.y, qd[3][2*i+1], a3);
        }
        // slim epilogue: 4 ops/query, carried dep = FMNMX only
        {
            float lo, hi; unpack2(a0, lo, hi);
            float pm  = fmaxf(lo, hi);
            bool  upd = pm > maxv[0];
            maxv[0] = fmaxf(maxv[0], pm);
            jpb[0]  = upd ? jp : jpb[0];
        }
        {
            float lo, hi; unpack2(a1, lo, hi);
            float pm  = fmaxf(lo, hi);
            bool  upd = pm > maxv[1];
            maxv[1] = fmaxf(maxv[1], pm);
            jpb[1]  = upd ? jp : jpb[1];
        }
        {
            float lo, hi; unpack2(a2, lo, hi);
            float pm  = fmaxf(lo, hi);
            bool  upd = pm > maxv[2];
            maxv[2] = fmaxf(maxv[2], pm);
            jpb[2]  = upd ? jp : jpb[2];
        }
        {
            float lo, hi; unpack2(a3, lo, hi);
            float pm  = fmaxf(lo, hi);
            bool  upd = pm > maxv[3];
            maxv[3] = fmaxf(maxv[3], pm);
            jpb[3]  = upd ? jp : jpb[3];
        }
    }

    // ---- disambiguate lo/hi within each winning pair (re-dot) ----
    int idx[4];
    #pragma unroll
    for (int qq = 0; qq < 4; qq++) {
        const ulonglong2* kp = (const ulonglong2*)(sk + jpb[qq] * DIN);
        u64 a = z2;
        #pragma unroll
        for (int i = 0; i < 7; i++) {
            ulonglong2 kk = kp[i];
            a = fma2(kk.x, qd[qq][2*i],   a);
            a = fma2(kk.y, qd[qq][2*i+1], a);
        }
        float lo, hi; unpack2(a, lo, hi);
        idx[qq] = 2 * jpb[qq] + ((hi > lo) ? 1 : 0);
    }

    // ---- head: z[n] = sum_s Wb[s]*c[idx(s)][n] (+bias), softmax over 7 ----
    float zp[NC];
    #pragma unroll
    for (int n = 0; n < NC; n++) zp[n] = 0.f;
    #pragma unroll
    for (int p = 0; p < 4; p++) {
        int id = idx[p];
        float w = swb[s0 + p];
        const float4* cr = (const float4*)(g_c8 + id * 8);
        float4 c0 = __ldg(cr);
        float4 c1 = __ldg(cr + 1);
        zp[0] += w * c0.x; zp[1] += w * c0.y; zp[2] += w * c0.z; zp[3] += w * c0.w;
        zp[4] += w * c1.x; zp[5] += w * c1.y; zp[6] += w * c1.z;
    }
    // combine the 4 quarter-row threads (t..t^3, same b, same warp)
    #pragma unroll
    for (int n = 0; n < NC; n++) {
        zp[n] += __shfl_xor_sync(0xffffffffu, zp[n], 1);
        zp[n] += __shfl_xor_sync(0xffffffffu, zp[n], 2);
    }

    if (valid && ((t & 3) == 0)) {
        float sumWb = 0.f;
        #pragma unroll
        for (int s = 0; s < SB; s++) sumWb += swb[s];
        float z[NC], zmax = -CUDART_INF_F;
        #pragma unroll
        for (int n = 0; n < NC; n++) {
            z[n] = zp[n] + sbm[n] * sumWb + sbb;
            zmax = fmaxf(zmax, z[n]);
        }
        float es = 0.f;
        #pragma unroll
        for (int n = 0; n < NC; n++) { z[n] = expf(z[n] - zmax); es += z[n]; }
        float inv = 1.0f / es;
        float* op = out + (size_t)b * NC;
        #pragma unroll
        for (int n = 0; n < NC; n++) op[n] = z[n] * inv;
    }
}

// ============================================================
extern "C" void kernel_launch(void* const* d_in, const int* in_sizes, int n_in,
                              void* d_out, int out_size) {
    const float* x      = (const float*)d_in[0];
    const float* lookup = (const float*)d_in[1];
    const float* g_st   = (const float*)d_in[2];
    const float* b_st   = (const float*)d_in[3];
    const float* g_sp   = (const float*)d_in[4];
    const float* b_sp   = (const float*)d_in[5];
    const float* g_pp   = (const float*)d_in[6];
    const float* b_pp   = (const float*)d_in[7];
    const float* Wv     = (const float*)d_in[8];
    const float* Wo     = (const float*)d_in[9];
    const float* Wm     = (const float*)d_in[10];
    const float* bm     = (const float*)d_in[11];
    const float* Wb     = (const float*)d_in[12];
    const float* bb     = (const float*)d_in[13];
    float* out = (float*)d_out;

    int B = in_sizes[0] / (SB * DIN);

    prep_all<<<QN, 128>>>(lookup, g_st, b_st, g_pp, b_pp, Wv, Wo, Wm);
    hopfield_main<<<(B + 31) / 32, 128>>>(x, g_sp, b_sp, bm, Wb, bb, out, B);
}